// round 5
// baseline (speedup 1.0000x reference)
#include <cuda_runtime.h>
#include <cuda_bf16.h>

// SpanGenerator: out = concat_{L=1..8} [ sliding sums of length L starting at
// token index 1 ] over input [B=8, S=512, D=768] fp32.
// span(L, i) = sum_{k=1+i}^{L+i} x[b, k, :],  valid for 0 <= i <= S-1-L.
// Output row offset for span-length L: OFF[L-1] = sum_{l<L} (S - l).

#define BB 8
#define SS 512
#define DD 768
#define D4 (DD / 4)      // 192 float4 lanes
#define NROWS 4060       // sum_{L=1..8} (512 - L)
#define ICHUNK 4

__global__ __launch_bounds__(D4, 8)
void span_kernel(const float4* __restrict__ in, float4* __restrict__ out) {
    const int d  = threadIdx.x;            // 0..191 (float4 index in D)
    const int b  = blockIdx.y;             // batch
    const int i0 = blockIdx.x * ICHUNK;    // start span-index for this chunk

    const float4* src  = in  + (size_t)b * SS * D4 + d;
    float4*       dstb = out + (size_t)b * NROWS * D4 + d;

    const float4 fzero = make_float4(0.f, 0.f, 0.f, 0.f);

    // Row offsets of each span-length block in the concatenated output.
    const int OFF[8] = {0, 511, 1021, 1530, 2038, 2545, 3051, 3556};

    // Per-L destination pointers for row i0 (advanced by D4 each iteration).
    float4* dstL[8];
#pragma unroll
    for (int L = 0; L < 8; L++) dstL[L] = dstb + (size_t)(OFF[L] + i0) * D4;

    // Sliding window of 8 input rows: w[k] = x[b, 1 + i + k, dquad]
    float4 w[8];
#pragma unroll
    for (int k = 0; k < 7; k++) {
        int s = 1 + i0 + k;
        w[k] = (s < SS) ? src[(size_t)s * D4] : fzero;
    }

    if (i0 + ICHUNK <= SS - 8) {
        // Fast path: every load and all 8 stores are valid for all i in chunk.
#pragma unroll
        for (int t = 0; t < ICHUNK; t++) {
            const int i = i0 + t;
            w[7] = src[(size_t)(i + 8) * D4];

            float4 acc = fzero;
#pragma unroll
            for (int L = 0; L < 8; L++) {
                acc.x += w[L].x;
                acc.y += w[L].y;
                acc.z += w[L].z;
                acc.w += w[L].w;
                __stcs(dstL[L], acc);   // streaming store: output is write-once
                dstL[L] += D4;
            }
#pragma unroll
            for (int k = 0; k < 7; k++) w[k] = w[k + 1];
        }
    } else {
        // Tail path: guard loads and stores against the sequence end.
        const int iend = min(i0 + ICHUNK, SS - 1);   // i ranges over [0, 510]
        for (int i = i0; i < iend; i++) {
            {
                int s = i + 8;
                w[7] = (s < SS) ? src[(size_t)s * D4] : fzero;
            }
            float4 acc = fzero;
#pragma unroll
            for (int L = 0; L < 8; L++) {
                acc.x += w[L].x;
                acc.y += w[L].y;
                acc.z += w[L].z;
                acc.w += w[L].w;
                if (i + L + 1 < SS) {
                    __stcs(dstL[L], acc);
                }
                dstL[L] += D4;
            }
#pragma unroll
            for (int k = 0; k < 7; k++) w[k] = w[k + 1];
        }
    }
}

extern "C" void kernel_launch(void* const* d_in, const int* in_sizes, int n_in,
                              void* d_out, int out_size) {
    const float4* in  = (const float4*)d_in[0];   // tensor [8, 512, 768] fp32
    float4*       out = (float4*)d_out;           // [8, 4060, 768] fp32
    (void)in_sizes; (void)n_in; (void)out_size;   // max_span_length fixed at 8

    dim3 grid((SS - 1 + ICHUNK - 1) / ICHUNK, BB);  // (128, 8)
    dim3 block(D4);                                  // 192 threads
    span_kernel<<<grid, block>>>(in, out);
}

// round 6
// speedup vs baseline: 1.0082x; 1.0082x over previous
#include <cuda_runtime.h>
#include <cuda_bf16.h>

// SpanGenerator: out = concat_{L=1..8} [ sliding sums of length L starting at
// token index 1 ] over input [B=8, S=512, D=768] fp32.
// span(L, i) = sum_{k=1+i}^{L+i} x[b, k, :],  valid for 0 <= i <= S-1-L.
// Output row offset for span-length L: OFF[L-1] = sum_{l<L} (S - l).

#define BB 8
#define SS 512
#define DD 768
#define D4 (DD / 4)      // 192 float4 lanes
#define NROWS 4060       // sum_{L=1..8} (512 - L)
#define ICHUNK 4

__global__ __launch_bounds__(D4, 8)
void span_kernel(const float4* __restrict__ in, float4* __restrict__ out) {
    const int d  = threadIdx.x;            // 0..191 (float4 index in D)
    const int b  = blockIdx.y;             // batch
    const int i0 = blockIdx.x * ICHUNK;    // start span-index for this chunk

    const float4* src  = in  + (size_t)b * SS * D4 + d;
    float4*       dstb = out + (size_t)b * NROWS * D4 + d;

    const float4 fzero = make_float4(0.f, 0.f, 0.f, 0.f);

    // Row offsets of each span-length block in the concatenated output.
    const int OFF[8] = {0, 511, 1021, 1530, 2038, 2545, 3051, 3556};

    // Per-L destination pointers for row i0 (advanced by D4 each iteration).
    float4* dstL[8];
#pragma unroll
    for (int L = 0; L < 8; L++) dstL[L] = dstb + (size_t)(OFF[L] + i0) * D4;

    // Sliding window of 8 input rows: w[k] = x[b, 1 + i + k, dquad]
    float4 w[8];
#pragma unroll
    for (int k = 0; k < 7; k++) {
        int s = 1 + i0 + k;
        w[k] = (s < SS) ? src[(size_t)s * D4] : fzero;
    }

    if (i0 + ICHUNK <= SS - 8) {
        // Fast path: every load and all 8 stores are valid for all i in chunk.
#pragma unroll
        for (int t = 0; t < ICHUNK; t++) {
            const int i = i0 + t;
            w[7] = src[(size_t)(i + 8) * D4];

            float4 acc = fzero;
#pragma unroll
            for (int L = 0; L < 8; L++) {
                acc.x += w[L].x;
                acc.y += w[L].y;
                acc.z += w[L].z;
                acc.w += w[L].w;
                dstL[L][0] = acc;       // plain STG.128 (no cache hint)
                dstL[L] += D4;
            }
#pragma unroll
            for (int k = 0; k < 7; k++) w[k] = w[k + 1];
        }
    } else {
        // Tail path: guard loads and stores against the sequence end.
        const int iend = min(i0 + ICHUNK, SS - 1);   // i ranges over [0, 510]
        for (int i = i0; i < iend; i++) {
            {
                int s = i + 8;
                w[7] = (s < SS) ? src[(size_t)s * D4] : fzero;
            }
            float4 acc = fzero;
#pragma unroll
            for (int L = 0; L < 8; L++) {
                acc.x += w[L].x;
                acc.y += w[L].y;
                acc.z += w[L].z;
                acc.w += w[L].w;
                if (i + L + 1 < SS) {
                    dstL[L][0] = acc;
                }
                dstL[L] += D4;
            }
#pragma unroll
            for (int k = 0; k < 7; k++) w[k] = w[k + 1];
        }
    }
}

extern "C" void kernel_launch(void* const* d_in, const int* in_sizes, int n_in,
                              void* d_out, int out_size) {
    const float4* in  = (const float4*)d_in[0];   // tensor [8, 512, 768] fp32
    float4*       out = (float4*)d_out;           // [8, 4060, 768] fp32
    (void)in_sizes; (void)n_in; (void)out_size;   // max_span_length fixed at 8

    dim3 grid((SS - 1 + ICHUNK - 1) / ICHUNK, BB);  // (128, 8)
    dim3 block(D4);                                  // 192 threads
    span_kernel<<<grid, block>>>(in, out);
}

// round 8
// speedup vs baseline: 1.5709x; 1.5581x over previous
#include <cuda_runtime.h>
#include <cuda_bf16.h>
#include <cstdint>

// SpanGenerator: out = concat_{L=1..8} [ sliding sums of length L starting at
// token index 1 ] over input [B=8, S=512, D=768] fp32.
// span(L, i) = sum_{k=1+i}^{L+i} x[b, k, :],  valid for 0 <= i <= S-1-L.
//
// Strategy: compute ICHUNK span-indices per block in registers, stage all 8
// span-length outputs in SMEM, and drain each L's contiguous rows to GMEM with
// one cp.async.bulk (1-D TMA bulk store). Stores never occupy warp issue slots.

#define BB 8
#define SS 512
#define DD 768
#define D4 (DD / 4)          // 192 float4 lanes
#define NROWS 4060           // sum_{L=1..8} (512 - L)
#define ICHUNK 4
#define ROWB (DD * 4)        // 3072 bytes per output row
#define SMEM_BYTES (8 * ICHUNK * ROWB)   // 98304 B = 96 KB

__global__ __launch_bounds__(D4, 2)
void span_kernel(const float4* __restrict__ in, float4* __restrict__ out) {
    extern __shared__ float4 sm[];       // [8 L][ICHUNK rows][D4]

    const int d  = threadIdx.x;          // 0..191 (float4 index in D)
    const int b  = blockIdx.y;           // batch
    const int i0 = blockIdx.x * ICHUNK;  // first span-index of this chunk

    const float4* src = in + (size_t)b * SS * D4 + d;

    // Front-batched window: w[k] = x[b, 1 + i0 + k, dquad], k = 0..ICHUNK+6.
    // Clamp the row index instead of branching; rows that would be out of
    // bounds only feed outputs that are never copied out.
    float4 w[ICHUNK + 7];
#pragma unroll
    for (int k = 0; k < ICHUNK + 7; k++) {
        int s = 1 + i0 + k;
        s = (s < SS - 1) ? s : (SS - 1);
        w[k] = src[(size_t)s * D4];
    }

    // Output (i = i0 + t, span L+1) = sum_{k=t}^{t+L} w[k]  -> smem stage.
#pragma unroll
    for (int t = 0; t < ICHUNK; t++) {
        float4 acc = make_float4(0.f, 0.f, 0.f, 0.f);
#pragma unroll
        for (int L = 0; L < 8; L++) {
            acc.x += w[t + L].x;
            acc.y += w[t + L].y;
            acc.z += w[t + L].z;
            acc.w += w[t + L].w;
            sm[(size_t)(L * ICHUNK + t) * D4 + d] = acc;
        }
    }

    __syncthreads();
    asm volatile("fence.proxy.async.shared::cta;" ::: "memory");

    // One bulk store per span-length L: rows [i0, i0+rows) of L's block are
    // contiguous in GMEM (row stride == D4 within each L segment).
    if (threadIdx.x < 8) {
        const int L = threadIdx.x;                       // span length L+1
        int rows = SS - (L + 1) - i0;                    // valid i count
        rows = (rows < ICHUNK) ? rows : ICHUNK;
        if (rows > 0) {
            const int OFF[8] = {0, 511, 1021, 1530, 2038, 2545, 3051, 3556};
            float4* dst = out + ((size_t)b * NROWS + OFF[L] + i0) * D4;
            uint32_t saddr =
                (uint32_t)__cvta_generic_to_shared(sm + (size_t)(L * ICHUNK) * D4);
            asm volatile(
                "cp.async.bulk.global.shared::cta.bulk_group [%0], [%1], %2;"
                :: "l"(dst), "r"(saddr), "r"(rows * ROWB) : "memory");
        }
        asm volatile("cp.async.bulk.commit_group;" ::: "memory");
        asm volatile("cp.async.bulk.wait_group 0;" ::: "memory");
    }
}

extern "C" void kernel_launch(void* const* d_in, const int* in_sizes, int n_in,
                              void* d_out, int out_size) {
    const float4* in  = (const float4*)d_in[0];   // tensor [8, 512, 768] fp32
    float4*       out = (float4*)d_out;           // [8, 4060, 768] fp32
    (void)in_sizes; (void)n_in; (void)out_size;   // max_span_length fixed at 8

    cudaFuncSetAttribute(span_kernel,
                         cudaFuncAttributeMaxDynamicSharedMemorySize, SMEM_BYTES);

    dim3 grid((SS - 1 + ICHUNK - 1) / ICHUNK, BB);  // (128, 8)
    dim3 block(D4);                                  // 192 threads
    span_kernel<<<grid, block, SMEM_BYTES>>>(in, out);
}

// round 10
// speedup vs baseline: 1.7060x; 1.0860x over previous
#include <cuda_runtime.h>
#include <cuda_bf16.h>
#include <cstdint>

// SpanGenerator: out = concat_{L=1..8} [ sliding sums of length L starting at
// token index 1 ] over input [B=8, S=512, D=768] fp32.
// span(L, i) = sum_{k=1+i}^{L+i} x[b, k, :],  valid for 0 <= i <= S-1-L.
//
// Pipelined bulk-store version: per block, 4 iterations x 2 span-indices,
// double-buffered SMEM stage drained by cp.async.bulk (1-D TMA). wait_group 1
// inside the loop keeps one drain in flight while computing the next buffer;
// only the last drain is exposed.

#define BB 8
#define SS 512
#define DD 768
#define D4 (DD / 4)          // 192 float4 lanes
#define NROWS 4060           // sum_{L=1..8} (512 - L)
#define ROWB (DD * 4)        // 3072 bytes per output row

#define ICH 2                // span-indices per iteration
#define ITERS 4              // iterations per block
#define CHUNK (ICH * ITERS)  // 8 span-indices per block
#define BUF_ROWS (8 * ICH)           // 16 rows per buffer
#define BUF_F4 (BUF_ROWS * D4)
#define SMEM_BYTES (2 * BUF_ROWS * ROWB)   // 96 KB (two 48 KB buffers)

__global__ __launch_bounds__(D4, 2)
void span_kernel(const float4* __restrict__ in, float4* __restrict__ out) {
    extern __shared__ float4 sm[];       // [2][8 L][ICH rows][D4]

    const int d  = threadIdx.x;          // 0..191 (float4 index in D)
    const int b  = blockIdx.y;           // batch
    const int i0 = blockIdx.x * CHUNK;   // first span-index of this block

    const float4* src = in + (size_t)b * SS * D4 + d;
    const int OFF[8] = {0, 511, 1021, 1530, 2038, 2545, 3051, 3556};

    // Sliding window w[k] = x[b, 1 + i + k, dquad], k = 0..ICH+6 (9 rows).
    // Clamp row index: clamped rows only feed outputs that are never drained.
    float4 w[ICH + 7];
#pragma unroll
    for (int k = 0; k < ICH + 7; k++) {
        int s = 1 + i0 + k;
        s = (s < SS - 1) ? s : (SS - 1);
        w[k] = src[(size_t)s * D4];
    }

    int p = 0;
#pragma unroll
    for (int it = 0; it < ITERS; it++) {
        const int i = i0 + it * ICH;

        // Prefetch the next iteration's 2 window rows (latency hidden under
        // this iteration's compute + drain).
        float4 n0, n1;
        {
            int s0 = 1 + i + ICH + 7;
            int s1 = s0 + 1;
            s0 = (s0 < SS - 1) ? s0 : (SS - 1);
            s1 = (s1 < SS - 1) ? s1 : (SS - 1);
            n0 = src[(size_t)s0 * D4];
            n1 = src[(size_t)s1 * D4];
        }

        float4* buf = sm + p * BUF_F4;
#pragma unroll
        for (int t = 0; t < ICH; t++) {
            float4 acc = make_float4(0.f, 0.f, 0.f, 0.f);
#pragma unroll
            for (int L = 0; L < 8; L++) {
                acc.x += w[t + L].x;
                acc.y += w[t + L].y;
                acc.z += w[t + L].z;
                acc.w += w[t + L].w;
                buf[(size_t)(L * ICH + t) * D4 + d] = acc;
            }
        }

        __syncthreads();
        asm volatile("fence.proxy.async.shared::cta;" ::: "memory");

        if (threadIdx.x < 8) {
            const int L = threadIdx.x;                 // span length L+1
            int rows = SS - (L + 1) - i;               // valid i count from i
            rows = (rows < ICH) ? rows : ICH;
            if (rows > 0) {
                float4* dst = out + ((size_t)b * NROWS + OFF[L] + i) * D4;
                uint32_t saddr = (uint32_t)__cvta_generic_to_shared(
                    buf + (size_t)(L * ICH) * D4);
                asm volatile(
                    "cp.async.bulk.global.shared::cta.bulk_group [%0], [%1], %2;"
                    :: "l"(dst), "r"(saddr), "r"(rows * ROWB) : "memory");
            }
            asm volatile("cp.async.bulk.commit_group;" ::: "memory");
            // Keep the just-committed drain in flight; ensure the drain of the
            // OTHER buffer (committed last iteration) has finished so it can
            // be overwritten next iteration.
            asm volatile("cp.async.bulk.wait_group 1;" ::: "memory");
        }
        __syncthreads();

        // Slide the window by ICH.
#pragma unroll
        for (int k = 0; k < 7; k++) w[k] = w[k + ICH];
        w[7] = n0;
        w[8] = n1;
        p ^= 1;
    }

    // Final drain: only the last buffer's copies remain outstanding.
    if (threadIdx.x < 8) {
        asm volatile("cp.async.bulk.wait_group 0;" ::: "memory");
    }
}

extern "C" void kernel_launch(void* const* d_in, const int* in_sizes, int n_in,
                              void* d_out, int out_size) {
    const float4* in  = (const float4*)d_in[0];   // tensor [8, 512, 768] fp32
    float4*       out = (float4*)d_out;           // [8, 4060, 768] fp32
    (void)in_sizes; (void)n_in; (void)out_size;   // max_span_length fixed at 8

    cudaFuncSetAttribute(span_kernel,
                         cudaFuncAttributeMaxDynamicSharedMemorySize, SMEM_BYTES);

    dim3 grid((SS - 1 + CHUNK - 1) / CHUNK, BB);    // (64, 8)
    dim3 block(D4);                                  // 192 threads
    span_kernel<<<grid, block, SMEM_BYTES>>>(in, out);
}